// round 12
// baseline (speedup 1.0000x reference)
#include <cuda_runtime.h>
#include <math.h>

#define DIM      4096
#define BATCH    8192
#define NLAYERS  6
#define EPS      1e-12f
#define MAXNORM  10.0f

// Output layout (fp32, concatenated in reference return order):
//   h_final  : [BATCH, DIM]            offset 0
//   aligns   : [NLAYERS, BATCH, 3]     offset TRACE_A
//   divs     : [NLAYERS, BATCH, 3]     offset TRACE_D
//   tensions : [NLAYERS, BATCH, 3]     offset TRACE_T
#define TRACE_A  ((size_t)BATCH * DIM)
#define TRACE_SZ ((size_t)NLAYERS * BATCH * 3)
#define TRACE_D  (TRACE_A + TRACE_SZ)
#define TRACE_T  (TRACE_D + TRACE_SZ)

__device__ float g_D[9];     // Gram of normalized anchor dirs
__device__ float g_invn[3];  // 1/max(||anchor_k||, eps)

// ---------------------------------------------------------------------------
// Prep: anchor norms + pairwise dots -> normalized-direction Gram. One block.
// ---------------------------------------------------------------------------
__global__ void prep_kernel(const float* __restrict__ aE,
                            const float* __restrict__ aC,
                            const float* __restrict__ aN) {
    float s[6] = {0.f, 0.f, 0.f, 0.f, 0.f, 0.f};  // EE, CC, NN, EC, EN, CN
    for (int i = threadIdx.x; i < DIM; i += 256) {
        float e = aE[i], c = aC[i], n = aN[i];
        s[0] = fmaf(e, e, s[0]);
        s[1] = fmaf(c, c, s[1]);
        s[2] = fmaf(n, n, s[2]);
        s[3] = fmaf(e, c, s[3]);
        s[4] = fmaf(e, n, s[4]);
        s[5] = fmaf(c, n, s[5]);
    }
    __shared__ float red[8][6];
    int lane = threadIdx.x & 31, w = threadIdx.x >> 5;
#pragma unroll
    for (int j = 0; j < 6; j++)
#pragma unroll
        for (int off = 16; off > 0; off >>= 1)
            s[j] += __shfl_down_sync(0xFFFFFFFFu, s[j], off);
    if (lane == 0)
#pragma unroll
        for (int j = 0; j < 6; j++) red[w][j] = s[j];
    __syncthreads();
    if (threadIdx.x == 0) {
        float t[6];
#pragma unroll
        for (int j = 0; j < 6; j++) {
            float acc = 0.f;
#pragma unroll
            for (int ww = 0; ww < 8; ww++) acc += red[ww][j];
            t[j] = acc;
        }
        float iE = 1.f / fmaxf(sqrtf(t[0]), EPS);
        float iC = 1.f / fmaxf(sqrtf(t[1]), EPS);
        float iN = 1.f / fmaxf(sqrtf(t[2]), EPS);
        g_invn[0] = iE; g_invn[1] = iC; g_invn[2] = iN;
        g_D[0] = t[0] * iE * iE;
        g_D[4] = t[1] * iC * iC;
        g_D[8] = t[2] * iN * iN;
        float ec = t[3] * iE * iC, en = t[4] * iE * iN, cn = t[5] * iC * iN;
        g_D[1] = ec; g_D[3] = ec;
        g_D[2] = en; g_D[6] = en;
        g_D[5] = cn; g_D[7] = cn;
    }
}

// ---------------------------------------------------------------------------
// Main: ONE WARP PER ROW, no smem, no barriers. 128-thr blocks (grid 2048)
// for fine wave granularity. h loads batched 8-deep (hbuf) to double DRAM
// MLP; anchors are L1-hot short-latency loads issued after the batch.
// Pass-2 h re-read uses __ldcs (last use, evict-first).
// ---------------------------------------------------------------------------
__global__ __launch_bounds__(128, 8) void collapse_kernel(
    const float* __restrict__ h0,
    const float* __restrict__ aE,
    const float* __restrict__ aC,
    const float* __restrict__ aN,
    float* __restrict__ out)
{
    const int row  = (blockIdx.x * blockDim.x + threadIdx.x) >> 5;
    const int lane = threadIdx.x & 31;
    if (row >= BATCH) return;

    const float4* hr = (const float4*)(h0 + (size_t)row * DIM);
    const float4* e4 = (const float4*)aE;
    const float4* c4 = (const float4*)aC;
    const float4* n4 = (const float4*)aN;

    // ---- pass 1: 4 fused dot products; h loads batched 8-deep ----
    float sH = 0.f, sE = 0.f, sC = 0.f, sN = 0.f;
#pragma unroll
    for (int g = 0; g < 4; g++) {            // 4 groups x 8 iters = 32
        float4 hbuf[8];
#pragma unroll
        for (int j = 0; j < 8; j++)
            hbuf[j] = hr[(g * 8 + j) * 32 + lane];
#pragma unroll
        for (int j = 0; j < 8; j++) {
            int i = (g * 8 + j) * 32 + lane;
            float4 h = hbuf[j];
            float4 e = e4[i], c = c4[i], n = n4[i];
            sH = fmaf(h.x, h.x, fmaf(h.y, h.y, fmaf(h.z, h.z, fmaf(h.w, h.w, sH))));
            sE = fmaf(h.x, e.x, fmaf(h.y, e.y, fmaf(h.z, e.z, fmaf(h.w, e.w, sE))));
            sC = fmaf(h.x, c.x, fmaf(h.y, c.y, fmaf(h.z, c.z, fmaf(h.w, c.w, sC))));
            sN = fmaf(h.x, n.x, fmaf(h.y, n.y, fmaf(h.z, n.z, fmaf(h.w, n.w, sN))));
        }
    }
#pragma unroll
    for (int off = 16; off > 0; off >>= 1) {
        sH += __shfl_down_sync(0xFFFFFFFFu, sH, off);
        sE += __shfl_down_sync(0xFFFFFFFFu, sE, off);
        sC += __shfl_down_sync(0xFFFFFFFFu, sC, off);
        sN += __shfl_down_sync(0xFFFFFFFFu, sN, off);
    }
    const float g00 = __shfl_sync(0xFFFFFFFFu, sH, 0);
    const float dE  = __shfl_sync(0xFFFFFFFFu, sE, 0);
    const float dC  = __shfl_sync(0xFFFFFFFFu, sC, 0);
    const float dN  = __shfl_sync(0xFFFFFFFFu, sN, 0);

    // ---- scalar 6-layer recurrence (all lanes redundant; MUFU-only) ----
    const float invn0 = g_invn[0], invn1 = g_invn[1], invn2 = g_invn[2];
    float g0[3] = { dE * invn0, dC * invn1, dN * invn2 };
    float D[9];
#pragma unroll
    for (int j = 0; j < 9; j++) D[j] = g_D[j];

    float c0 = 1.f;
    float cc[3] = { 0.f, 0.f, 0.f };
    const float str[3] = { 0.1f, 0.1f, 0.05f };

#pragma unroll
    for (int l = 0; l < NLAYERS; l++) {
        float hd[3];
#pragma unroll
        for (int k = 0; k < 3; k++)
            hd[k] = c0 * g0[k] + cc[0] * D[0 * 3 + k] + cc[1] * D[1 * 3 + k] + cc[2] * D[2 * 3 + k];
        float hh = c0 * (c0 * g00 + cc[0] * g0[0] + cc[1] * g0[1] + cc[2] * g0[2])
                 + cc[0] * hd[0] + cc[1] * hd[1] + cc[2] * hd[2];
        float inv = rsqrtf(fmaxf(hh, 1e-24f));   // 1/||h||

        float a[3];
#pragma unroll
        for (int k = 0; k < 3; k++) {
            float align = hd[k] * inv;
            float dv    = 1.f - align;
            float tens  = fmaxf(dv, 0.f);
            if (lane == 0) {
                size_t ti = (size_t)l * (BATCH * 3) + (size_t)row * 3 + k;
                __stcs(out + TRACE_A + ti, align);
                __stcs(out + TRACE_D + ti, dv);
                __stcs(out + TRACE_T + ti, tens);
            }
            float msq = fmaxf(hh - 2.f * hd[k] + D[k * 3 + k], 1e-24f);
            a[k] = str[k] * dv * rsqrtf(msq);    // str*dv/||h - dir_k||
        }
        float f = 1.f - (a[0] + a[1] + a[2]);
        c0 *= f;
        cc[0] = cc[0] * f + a[0];
        cc[1] = cc[1] * f + a[1];
        cc[2] = cc[2] * f + a[2];

        // ||h_new|| via Gram quadratic form; clamp to MAXNORM
        float hd2[3];
#pragma unroll
        for (int k = 0; k < 3; k++)
            hd2[k] = c0 * g0[k] + cc[0] * D[0 * 3 + k] + cc[1] * D[1 * 3 + k] + cc[2] * D[2 * 3 + k];
        float hh2 = c0 * (c0 * g00 + cc[0] * g0[0] + cc[1] * g0[1] + cc[2] * g0[2])
                  + cc[0] * hd2[0] + cc[1] * hd2[1] + cc[2] * hd2[2];
        float rn = rsqrtf(fmaxf(hh2, 1e-24f));
        float nn = hh2 * rn;                     // ||h_new||
        if (nn > MAXNORM) {
            float scl = MAXNORM * rn;            // 10/||h||
            c0 *= scl; cc[0] *= scl; cc[1] *= scl; cc[2] *= scl;
        }
    }
    const float wE = cc[0] * invn0, wC = cc[1] * invn1, wN = cc[2] * invn2;

    // ---- pass 2: h_final = c0*h + wE*E + wC*C + wN*N ----
    // h re-read batched 8-deep with .cs (last use); output streamed with .cs
    float4* orow = (float4*)(out + (size_t)row * DIM);
#pragma unroll
    for (int g = 0; g < 4; g++) {
        float4 hbuf[8];
#pragma unroll
        for (int j = 0; j < 8; j++)
            hbuf[j] = __ldcs(&hr[(g * 8 + j) * 32 + lane]);
#pragma unroll
        for (int j = 0; j < 8; j++) {
            int i = (g * 8 + j) * 32 + lane;
            float4 h = hbuf[j];
            float4 e = e4[i], c = c4[i], n = n4[i];
            float4 o;
            o.x = fmaf(c0, h.x, fmaf(wE, e.x, fmaf(wC, c.x, wN * n.x)));
            o.y = fmaf(c0, h.y, fmaf(wE, e.y, fmaf(wC, c.y, wN * n.y)));
            o.z = fmaf(c0, h.z, fmaf(wE, e.z, fmaf(wC, c.z, wN * n.z)));
            o.w = fmaf(c0, h.w, fmaf(wE, e.w, fmaf(wC, c.w, wN * n.w)));
            __stcs(&orow[i], o);
        }
    }
}

extern "C" void kernel_launch(void* const* d_in, const int* in_sizes, int n_in,
                              void* d_out, int out_size) {
    const float* h0 = (const float*)d_in[0];
    const float* aE = (const float*)d_in[1];
    const float* aC = (const float*)d_in[2];
    const float* aN = (const float*)d_in[3];
    float* out = (float*)d_out;

    prep_kernel<<<1, 256>>>(aE, aC, aN);
    // one warp per row: 8192 warps = 2048 blocks of 128 threads
    collapse_kernel<<<BATCH / 4, 128>>>(h0, aE, aC, aN, out);
}

// round 14
// speedup vs baseline: 1.1076x; 1.1076x over previous
#include <cuda_runtime.h>
#include <math.h>

#define DIM      4096
#define BATCH    8192
#define NLAYERS  6
#define EPS      1e-12f
#define MAXNORM  10.0f

// Output layout (fp32, concatenated in reference return order):
//   h_final  : [BATCH, DIM]            offset 0
//   aligns   : [NLAYERS, BATCH, 3]     offset TRACE_A
//   divs     : [NLAYERS, BATCH, 3]     offset TRACE_D
//   tensions : [NLAYERS, BATCH, 3]     offset TRACE_T
#define TRACE_A  ((size_t)BATCH * DIM)
#define TRACE_SZ ((size_t)NLAYERS * BATCH * 3)
#define TRACE_D  (TRACE_A + TRACE_SZ)
#define TRACE_T  (TRACE_D + TRACE_SZ)

__device__ float g_D[9];     // Gram of normalized anchor dirs
__device__ float g_invn[3];  // 1/max(||anchor_k||, eps)

// ---------------------------------------------------------------------------
// Prep: anchor norms + pairwise dots -> normalized-direction Gram. One block.
// ---------------------------------------------------------------------------
__global__ void prep_kernel(const float* __restrict__ aE,
                            const float* __restrict__ aC,
                            const float* __restrict__ aN) {
    float s[6] = {0.f, 0.f, 0.f, 0.f, 0.f, 0.f};  // EE, CC, NN, EC, EN, CN
    for (int i = threadIdx.x; i < DIM; i += 256) {
        float e = aE[i], c = aC[i], n = aN[i];
        s[0] = fmaf(e, e, s[0]);
        s[1] = fmaf(c, c, s[1]);
        s[2] = fmaf(n, n, s[2]);
        s[3] = fmaf(e, c, s[3]);
        s[4] = fmaf(e, n, s[4]);
        s[5] = fmaf(c, n, s[5]);
    }
    __shared__ float red[8][6];
    int lane = threadIdx.x & 31, w = threadIdx.x >> 5;
#pragma unroll
    for (int j = 0; j < 6; j++)
#pragma unroll
        for (int off = 16; off > 0; off >>= 1)
            s[j] += __shfl_down_sync(0xFFFFFFFFu, s[j], off);
    if (lane == 0)
#pragma unroll
        for (int j = 0; j < 6; j++) red[w][j] = s[j];
    __syncthreads();
    if (threadIdx.x == 0) {
        float t[6];
#pragma unroll
        for (int j = 0; j < 6; j++) {
            float acc = 0.f;
#pragma unroll
            for (int ww = 0; ww < 8; ww++) acc += red[ww][j];
            t[j] = acc;
        }
        float iE = 1.f / fmaxf(sqrtf(t[0]), EPS);
        float iC = 1.f / fmaxf(sqrtf(t[1]), EPS);
        float iN = 1.f / fmaxf(sqrtf(t[2]), EPS);
        g_invn[0] = iE; g_invn[1] = iC; g_invn[2] = iN;
        g_D[0] = t[0] * iE * iE;
        g_D[4] = t[1] * iC * iC;
        g_D[8] = t[2] * iN * iN;
        float ec = t[3] * iE * iC, en = t[4] * iE * iN, cn = t[5] * iC * iN;
        g_D[1] = ec; g_D[3] = ec;
        g_D[2] = en; g_D[6] = en;
        g_D[5] = cn; g_D[7] = cn;
    }
}

// ---------------------------------------------------------------------------
// Main: ONE WARP PER ROW, no smem, no barriers. h loads batched 8-deep in
// REGISTERS (no spill: launch_bounds(128,6) -> 85-reg budget). 24 warps/SM
// x 8 x 128B = 24.5 KB DRAM reads in flight per SM ~ bandwidth-latency
// product, so HBM stays saturated. Pass-2 h re-read via __ldcs.
// ---------------------------------------------------------------------------
__global__ __launch_bounds__(128, 6) void collapse_kernel(
    const float* __restrict__ h0,
    const float* __restrict__ aE,
    const float* __restrict__ aC,
    const float* __restrict__ aN,
    float* __restrict__ out)
{
    const int row  = (blockIdx.x * blockDim.x + threadIdx.x) >> 5;
    const int lane = threadIdx.x & 31;
    if (row >= BATCH) return;

    const float4* hr = (const float4*)(h0 + (size_t)row * DIM);
    const float4* e4 = (const float4*)aE;
    const float4* c4 = (const float4*)aC;
    const float4* n4 = (const float4*)aN;

    // ---- pass 1: 4 fused dot products; h loads batched 8-deep ----
    float sH = 0.f, sE = 0.f, sC = 0.f, sN = 0.f;
#pragma unroll
    for (int g = 0; g < 4; g++) {            // 4 groups x 8 iters = 32
        float4 hbuf[8];
#pragma unroll
        for (int j = 0; j < 8; j++)
            hbuf[j] = hr[(g * 8 + j) * 32 + lane];
#pragma unroll
        for (int j = 0; j < 8; j++) {
            int i = (g * 8 + j) * 32 + lane;
            float4 e = e4[i], c = c4[i], n = n4[i];
            float4 h = hbuf[j];
            sH = fmaf(h.x, h.x, fmaf(h.y, h.y, fmaf(h.z, h.z, fmaf(h.w, h.w, sH))));
            sE = fmaf(h.x, e.x, fmaf(h.y, e.y, fmaf(h.z, e.z, fmaf(h.w, e.w, sE))));
            sC = fmaf(h.x, c.x, fmaf(h.y, c.y, fmaf(h.z, c.z, fmaf(h.w, c.w, sC))));
            sN = fmaf(h.x, n.x, fmaf(h.y, n.y, fmaf(h.z, n.z, fmaf(h.w, n.w, sN))));
        }
    }
#pragma unroll
    for (int off = 16; off > 0; off >>= 1) {
        sH += __shfl_down_sync(0xFFFFFFFFu, sH, off);
        sE += __shfl_down_sync(0xFFFFFFFFu, sE, off);
        sC += __shfl_down_sync(0xFFFFFFFFu, sC, off);
        sN += __shfl_down_sync(0xFFFFFFFFu, sN, off);
    }
    const float g00 = __shfl_sync(0xFFFFFFFFu, sH, 0);
    const float dE  = __shfl_sync(0xFFFFFFFFu, sE, 0);
    const float dC  = __shfl_sync(0xFFFFFFFFu, sC, 0);
    const float dN  = __shfl_sync(0xFFFFFFFFu, sN, 0);

    // ---- scalar 6-layer recurrence (all lanes redundant; MUFU-only) ----
    const float invn0 = g_invn[0], invn1 = g_invn[1], invn2 = g_invn[2];
    float g0[3] = { dE * invn0, dC * invn1, dN * invn2 };
    float D[9];
#pragma unroll
    for (int j = 0; j < 9; j++) D[j] = g_D[j];

    float c0 = 1.f;
    float cc[3] = { 0.f, 0.f, 0.f };
    const float str[3] = { 0.1f, 0.1f, 0.05f };

#pragma unroll
    for (int l = 0; l < NLAYERS; l++) {
        float hd[3];
#pragma unroll
        for (int k = 0; k < 3; k++)
            hd[k] = c0 * g0[k] + cc[0] * D[0 * 3 + k] + cc[1] * D[1 * 3 + k] + cc[2] * D[2 * 3 + k];
        float hh = c0 * (c0 * g00 + cc[0] * g0[0] + cc[1] * g0[1] + cc[2] * g0[2])
                 + cc[0] * hd[0] + cc[1] * hd[1] + cc[2] * hd[2];
        float inv = rsqrtf(fmaxf(hh, 1e-24f));   // 1/||h||

        float a[3];
#pragma unroll
        for (int k = 0; k < 3; k++) {
            float align = hd[k] * inv;
            float dv    = 1.f - align;
            float tens  = fmaxf(dv, 0.f);
            if (lane == 0) {
                size_t ti = (size_t)l * (BATCH * 3) + (size_t)row * 3 + k;
                __stcs(out + TRACE_A + ti, align);
                __stcs(out + TRACE_D + ti, dv);
                __stcs(out + TRACE_T + ti, tens);
            }
            float msq = fmaxf(hh - 2.f * hd[k] + D[k * 3 + k], 1e-24f);
            a[k] = str[k] * dv * rsqrtf(msq);    // str*dv/||h - dir_k||
        }
        float f = 1.f - (a[0] + a[1] + a[2]);
        c0 *= f;
        cc[0] = cc[0] * f + a[0];
        cc[1] = cc[1] * f + a[1];
        cc[2] = cc[2] * f + a[2];

        // ||h_new|| via Gram quadratic form; clamp to MAXNORM
        float hd2[3];
#pragma unroll
        for (int k = 0; k < 3; k++)
            hd2[k] = c0 * g0[k] + cc[0] * D[0 * 3 + k] + cc[1] * D[1 * 3 + k] + cc[2] * D[2 * 3 + k];
        float hh2 = c0 * (c0 * g00 + cc[0] * g0[0] + cc[1] * g0[1] + cc[2] * g0[2])
                  + cc[0] * hd2[0] + cc[1] * hd2[1] + cc[2] * hd2[2];
        float rn = rsqrtf(fmaxf(hh2, 1e-24f));
        float nn = hh2 * rn;                     // ||h_new||
        if (nn > MAXNORM) {
            float scl = MAXNORM * rn;            // 10/||h||
            c0 *= scl; cc[0] *= scl; cc[1] *= scl; cc[2] *= scl;
        }
    }
    const float wE = cc[0] * invn0, wC = cc[1] * invn1, wN = cc[2] * invn2;

    // ---- pass 2: h_final = c0*h + wE*E + wC*C + wN*N ----
    // h re-read batched 8-deep with .cs (last use); output streamed with .cs
    float4* orow = (float4*)(out + (size_t)row * DIM);
#pragma unroll
    for (int g = 0; g < 4; g++) {
        float4 hbuf[8];
#pragma unroll
        for (int j = 0; j < 8; j++)
            hbuf[j] = __ldcs(&hr[(g * 8 + j) * 32 + lane]);
#pragma unroll
        for (int j = 0; j < 8; j++) {
            int i = (g * 8 + j) * 32 + lane;
            float4 e = e4[i], c = c4[i], n = n4[i];
            float4 h = hbuf[j];
            float4 o;
            o.x = fmaf(c0, h.x, fmaf(wE, e.x, fmaf(wC, c.x, wN * n.x)));
            o.y = fmaf(c0, h.y, fmaf(wE, e.y, fmaf(wC, c.y, wN * n.y)));
            o.z = fmaf(c0, h.z, fmaf(wE, e.z, fmaf(wC, c.z, wN * n.z)));
            o.w = fmaf(c0, h.w, fmaf(wE, e.w, fmaf(wC, c.w, wN * n.w)));
            __stcs(&orow[i], o);
        }
    }
}

extern "C" void kernel_launch(void* const* d_in, const int* in_sizes, int n_in,
                              void* d_out, int out_size) {
    const float* h0 = (const float*)d_in[0];
    const float* aE = (const float*)d_in[1];
    const float* aC = (const float*)d_in[2];
    const float* aN = (const float*)d_in[3];
    float* out = (float*)d_out;

    prep_kernel<<<1, 256>>>(aE, aC, aN);
    // one warp per row: 8192 warps = 2048 blocks of 128 threads
    collapse_kernel<<<BATCH / 4, 128>>>(h0, aE, aC, aN, out);
}

// round 15
// speedup vs baseline: 4.3360x; 3.9149x over previous
#include <cuda_runtime.h>
#include <math.h>

#define DIM      4096
#define BATCH    8192
#define NLAYERS  6
#define EPS      1e-12f
#define MAXNORM  10.0f

// Output layout (fp32, concatenated in reference return order):
//   h_final  : [BATCH, DIM]            offset 0
//   aligns   : [NLAYERS, BATCH, 3]     offset TRACE_A
//   divs     : [NLAYERS, BATCH, 3]     offset TRACE_D
//   tensions : [NLAYERS, BATCH, 3]     offset TRACE_T
#define TRACE_A  ((size_t)BATCH * DIM)
#define TRACE_SZ ((size_t)NLAYERS * BATCH * 3)
#define TRACE_D  (TRACE_A + TRACE_SZ)
#define TRACE_T  (TRACE_D + TRACE_SZ)

#define NWARPS   4096                    // total warps; each does 2 rows
#define ROWS_PER_WARP (BATCH / NWARPS)   // = 2

__device__ float g_D[9];     // Gram of normalized anchor dirs
__device__ float g_invn[3];  // 1/max(||anchor_k||, eps)

// ---------------------------------------------------------------------------
// Prep: anchor norms + pairwise dots -> normalized-direction Gram. One block.
// ---------------------------------------------------------------------------
__global__ void prep_kernel(const float* __restrict__ aE,
                            const float* __restrict__ aC,
                            const float* __restrict__ aN) {
    float s[6] = {0.f, 0.f, 0.f, 0.f, 0.f, 0.f};  // EE, CC, NN, EC, EN, CN
    for (int i = threadIdx.x; i < DIM; i += 256) {
        float e = aE[i], c = aC[i], n = aN[i];
        s[0] = fmaf(e, e, s[0]);
        s[1] = fmaf(c, c, s[1]);
        s[2] = fmaf(n, n, s[2]);
        s[3] = fmaf(e, c, s[3]);
        s[4] = fmaf(e, n, s[4]);
        s[5] = fmaf(c, n, s[5]);
    }
    __shared__ float red[8][6];
    int lane = threadIdx.x & 31, w = threadIdx.x >> 5;
#pragma unroll
    for (int j = 0; j < 6; j++)
#pragma unroll
        for (int off = 16; off > 0; off >>= 1)
            s[j] += __shfl_down_sync(0xFFFFFFFFu, s[j], off);
    if (lane == 0)
#pragma unroll
        for (int j = 0; j < 6; j++) red[w][j] = s[j];
    __syncthreads();
    if (threadIdx.x == 0) {
        float t[6];
#pragma unroll
        for (int j = 0; j < 6; j++) {
            float acc = 0.f;
#pragma unroll
            for (int ww = 0; ww < 8; ww++) acc += red[ww][j];
            t[j] = acc;
        }
        float iE = 1.f / fmaxf(sqrtf(t[0]), EPS);
        float iC = 1.f / fmaxf(sqrtf(t[1]), EPS);
        float iN = 1.f / fmaxf(sqrtf(t[2]), EPS);
        g_invn[0] = iE; g_invn[1] = iC; g_invn[2] = iN;
        g_D[0] = t[0] * iE * iE;
        g_D[4] = t[1] * iC * iC;
        g_D[8] = t[2] * iN * iN;
        float ec = t[3] * iE * iC, en = t[4] * iE * iN, cn = t[5] * iC * iN;
        g_D[1] = ec; g_D[3] = ec;
        g_D[2] = en; g_D[6] = en;
        g_D[5] = cn; g_D[7] = cn;
    }
}

// ---------------------------------------------------------------------------
// Main: one warp handles 2 rows sequentially; grid = 1024 blocks x 128 thr =
// 4096 warps -> SINGLE WAVE (all blocks co-resident, ~28 warps/SM), perfectly
// balanced, no barriers. Cross-row pipelining hides the serial recurrence:
// a warp's next-row loads start right after the previous row's stores.
// No register arrays (spill-proof, ~50 regs like R10).
// ---------------------------------------------------------------------------
__global__ __launch_bounds__(128, 8) void collapse_kernel(
    const float* __restrict__ h0,
    const float* __restrict__ aE,
    const float* __restrict__ aC,
    const float* __restrict__ aN,
    float* __restrict__ out)
{
    const int gwarp = (blockIdx.x * blockDim.x + threadIdx.x) >> 5;
    const int lane  = threadIdx.x & 31;

    const float4* e4 = (const float4*)aE;
    const float4* c4 = (const float4*)aC;
    const float4* n4 = (const float4*)aN;

#pragma unroll 1
    for (int r = 0; r < ROWS_PER_WARP; r++) {
        const int row = gwarp + r * NWARPS;
        const float4* hr = (const float4*)(h0 + (size_t)row * DIM);

        // ---- pass 1: 4 fused dot products over the row ----
        float sH = 0.f, sE = 0.f, sC = 0.f, sN = 0.f;
#pragma unroll 4
        for (int it = 0; it < DIM / 4 / 32; it++) {
            int i = it * 32 + lane;
            float4 h = hr[i];
            float4 e = e4[i], c = c4[i], n = n4[i];
            sH = fmaf(h.x, h.x, fmaf(h.y, h.y, fmaf(h.z, h.z, fmaf(h.w, h.w, sH))));
            sE = fmaf(h.x, e.x, fmaf(h.y, e.y, fmaf(h.z, e.z, fmaf(h.w, e.w, sE))));
            sC = fmaf(h.x, c.x, fmaf(h.y, c.y, fmaf(h.z, c.z, fmaf(h.w, c.w, sC))));
            sN = fmaf(h.x, n.x, fmaf(h.y, n.y, fmaf(h.z, n.z, fmaf(h.w, n.w, sN))));
        }
#pragma unroll
        for (int off = 16; off > 0; off >>= 1) {
            sH += __shfl_down_sync(0xFFFFFFFFu, sH, off);
            sE += __shfl_down_sync(0xFFFFFFFFu, sE, off);
            sC += __shfl_down_sync(0xFFFFFFFFu, sC, off);
            sN += __shfl_down_sync(0xFFFFFFFFu, sN, off);
        }
        const float g00 = __shfl_sync(0xFFFFFFFFu, sH, 0);
        const float dE  = __shfl_sync(0xFFFFFFFFu, sE, 0);
        const float dC  = __shfl_sync(0xFFFFFFFFu, sC, 0);
        const float dN  = __shfl_sync(0xFFFFFFFFu, sN, 0);

        // ---- scalar 6-layer recurrence (all lanes redundant; MUFU-only) ----
        const float invn0 = g_invn[0], invn1 = g_invn[1], invn2 = g_invn[2];
        float g0[3] = { dE * invn0, dC * invn1, dN * invn2 };
        float D[9];
#pragma unroll
        for (int j = 0; j < 9; j++) D[j] = g_D[j];

        float c0 = 1.f;
        float cc[3] = { 0.f, 0.f, 0.f };
        const float str[3] = { 0.1f, 0.1f, 0.05f };

#pragma unroll
        for (int l = 0; l < NLAYERS; l++) {
            float hd[3];
#pragma unroll
            for (int k = 0; k < 3; k++)
                hd[k] = c0 * g0[k] + cc[0] * D[0 * 3 + k] + cc[1] * D[1 * 3 + k] + cc[2] * D[2 * 3 + k];
            float hh = c0 * (c0 * g00 + cc[0] * g0[0] + cc[1] * g0[1] + cc[2] * g0[2])
                     + cc[0] * hd[0] + cc[1] * hd[1] + cc[2] * hd[2];
            float inv = rsqrtf(fmaxf(hh, 1e-24f));   // 1/||h||

            float a[3];
#pragma unroll
            for (int k = 0; k < 3; k++) {
                float align = hd[k] * inv;
                float dv    = 1.f - align;
                float tens  = fmaxf(dv, 0.f);
                if (lane == 0) {
                    size_t ti = (size_t)l * (BATCH * 3) + (size_t)row * 3 + k;
                    __stcs(out + TRACE_A + ti, align);
                    __stcs(out + TRACE_D + ti, dv);
                    __stcs(out + TRACE_T + ti, tens);
                }
                float msq = fmaxf(hh - 2.f * hd[k] + D[k * 3 + k], 1e-24f);
                a[k] = str[k] * dv * rsqrtf(msq);    // str*dv/||h - dir_k||
            }
            float f = 1.f - (a[0] + a[1] + a[2]);
            c0 *= f;
            cc[0] = cc[0] * f + a[0];
            cc[1] = cc[1] * f + a[1];
            cc[2] = cc[2] * f + a[2];

            // ||h_new|| via Gram quadratic form; clamp to MAXNORM
            float hd2[3];
#pragma unroll
            for (int k = 0; k < 3; k++)
                hd2[k] = c0 * g0[k] + cc[0] * D[0 * 3 + k] + cc[1] * D[1 * 3 + k] + cc[2] * D[2 * 3 + k];
            float hh2 = c0 * (c0 * g00 + cc[0] * g0[0] + cc[1] * g0[1] + cc[2] * g0[2])
                      + cc[0] * hd2[0] + cc[1] * hd2[1] + cc[2] * hd2[2];
            float rn = rsqrtf(fmaxf(hh2, 1e-24f));
            float nn = hh2 * rn;                     // ||h_new||
            if (nn > MAXNORM) {
                float scl = MAXNORM * rn;            // 10/||h||
                c0 *= scl; cc[0] *= scl; cc[1] *= scl; cc[2] *= scl;
            }
        }
        const float wE = cc[0] * invn0, wC = cc[1] * invn1, wN = cc[2] * invn2;

        // ---- pass 2: h_final = c0*h + wE*E + wC*C + wN*N ----
        float4* orow = (float4*)(out + (size_t)row * DIM);
#pragma unroll 4
        for (int it = 0; it < DIM / 4 / 32; it++) {
            int i = it * 32 + lane;
            float4 h = __ldcs(&hr[i]);               // last use of this row
            float4 e = e4[i], c = c4[i], n = n4[i];
            float4 o;
            o.x = fmaf(c0, h.x, fmaf(wE, e.x, fmaf(wC, c.x, wN * n.x)));
            o.y = fmaf(c0, h.y, fmaf(wE, e.y, fmaf(wC, c.y, wN * n.y)));
            o.z = fmaf(c0, h.z, fmaf(wE, e.z, fmaf(wC, c.z, wN * n.z)));
            o.w = fmaf(c0, h.w, fmaf(wE, e.w, fmaf(wC, c.w, wN * n.w)));
            __stcs(&orow[i], o);
        }
    }
}

extern "C" void kernel_launch(void* const* d_in, const int* in_sizes, int n_in,
                              void* d_out, int out_size) {
    const float* h0 = (const float*)d_in[0];
    const float* aE = (const float*)d_in[1];
    const float* aC = (const float*)d_in[2];
    const float* aN = (const float*)d_in[3];
    float* out = (float*)d_out;

    prep_kernel<<<1, 256>>>(aE, aC, aN);
    // 4096 warps = 1024 blocks x 128 thr; each warp does rows w and w+4096.
    collapse_kernel<<<NWARPS / 4, 128>>>(h0, aE, aC, aN, out);
}

// round 16
// speedup vs baseline: 4.3809x; 1.0104x over previous
#include <cuda_runtime.h>
#include <math.h>

#define DIM      4096
#define BATCH    8192
#define NLAYERS  6
#define EPS      1e-12f
#define MAXNORM  10.0f

// Output layout (fp32, concatenated in reference return order):
//   h_final  : [BATCH, DIM]            offset 0
//   aligns   : [NLAYERS, BATCH, 3]     offset TRACE_A
//   divs     : [NLAYERS, BATCH, 3]     offset TRACE_D
//   tensions : [NLAYERS, BATCH, 3]     offset TRACE_T
#define TRACE_A  ((size_t)BATCH * DIM)
#define TRACE_SZ ((size_t)NLAYERS * BATCH * 3)
#define TRACE_D  (TRACE_A + TRACE_SZ)
#define TRACE_T  (TRACE_D + TRACE_SZ)

#define NWARPS   4096                    // each warp owns rows w and w+NWARPS

__device__ float g_D[9];     // Gram of normalized anchor dirs
__device__ float g_invn[3];  // 1/max(||anchor_k||, eps)

// ---------------------------------------------------------------------------
// Prep: anchor norms + pairwise dots -> normalized-direction Gram. One block.
// ---------------------------------------------------------------------------
__global__ void prep_kernel(const float* __restrict__ aE,
                            const float* __restrict__ aC,
                            const float* __restrict__ aN) {
    float s[6] = {0.f, 0.f, 0.f, 0.f, 0.f, 0.f};  // EE, CC, NN, EC, EN, CN
    for (int i = threadIdx.x; i < DIM; i += 256) {
        float e = aE[i], c = aC[i], n = aN[i];
        s[0] = fmaf(e, e, s[0]);
        s[1] = fmaf(c, c, s[1]);
        s[2] = fmaf(n, n, s[2]);
        s[3] = fmaf(e, c, s[3]);
        s[4] = fmaf(e, n, s[4]);
        s[5] = fmaf(c, n, s[5]);
    }
    __shared__ float red[8][6];
    int lane = threadIdx.x & 31, w = threadIdx.x >> 5;
#pragma unroll
    for (int j = 0; j < 6; j++)
#pragma unroll
        for (int off = 16; off > 0; off >>= 1)
            s[j] += __shfl_down_sync(0xFFFFFFFFu, s[j], off);
    if (lane == 0)
#pragma unroll
        for (int j = 0; j < 6; j++) red[w][j] = s[j];
    __syncthreads();
    if (threadIdx.x == 0) {
        float t[6];
#pragma unroll
        for (int j = 0; j < 6; j++) {
            float acc = 0.f;
#pragma unroll
            for (int ww = 0; ww < 8; ww++) acc += red[ww][j];
            t[j] = acc;
        }
        float iE = 1.f / fmaxf(sqrtf(t[0]), EPS);
        float iC = 1.f / fmaxf(sqrtf(t[1]), EPS);
        float iN = 1.f / fmaxf(sqrtf(t[2]), EPS);
        g_invn[0] = iE; g_invn[1] = iC; g_invn[2] = iN;
        g_D[0] = t[0] * iE * iE;
        g_D[4] = t[1] * iC * iC;
        g_D[8] = t[2] * iN * iN;
        float ec = t[3] * iE * iC, en = t[4] * iE * iN, cn = t[5] * iC * iN;
        g_D[1] = ec; g_D[3] = ec;
        g_D[2] = en; g_D[6] = en;
        g_D[5] = cn; g_D[7] = cn;
    }
}

// ---------------------------------------------------------------------------
// Main: one warp processes TWO rows INTERLEAVED. Anchors loaded once per
// iteration serve both rows (L1 accesses per 2 rows: 18 -> 12), and the two
// independent h loads per iteration double DRAM MLP. The two scalar
// recurrences run concurrently on half-warps (lanes 0-15 row A, 16-31 row B).
// Single wave: 1024 blocks x 128 thr, launch_bounds(128,7) -> 7 blocks/SM,
// 148*7=1036 >= 1024. No smem, no barriers, no register arrays.
// ---------------------------------------------------------------------------
__global__ __launch_bounds__(128, 7) void collapse_kernel(
    const float* __restrict__ h0,
    const float* __restrict__ aE,
    const float* __restrict__ aC,
    const float* __restrict__ aN,
    float* __restrict__ out)
{
    const int gwarp = (blockIdx.x * blockDim.x + threadIdx.x) >> 5;
    const int lane  = threadIdx.x & 31;
    const int rowA  = gwarp;
    const int rowB  = gwarp + NWARPS;

    const float4* e4  = (const float4*)aE;
    const float4* c4  = (const float4*)aC;
    const float4* n4  = (const float4*)aN;
    const float4* hra = (const float4*)(h0 + (size_t)rowA * DIM);
    const float4* hrb = (const float4*)(h0 + (size_t)rowB * DIM);

    // ---- pass 1: 8 fused dot products (4 per row), anchors loaded once ----
    float aH = 0.f, aE_ = 0.f, aC_ = 0.f, aN_ = 0.f;
    float bH = 0.f, bE_ = 0.f, bC_ = 0.f, bN_ = 0.f;
#pragma unroll 2
    for (int it = 0; it < DIM / 4 / 32; it++) {
        int i = it * 32 + lane;
        float4 ha = hra[i];
        float4 hb = hrb[i];
        float4 e = e4[i], c = c4[i], n = n4[i];
        aH  = fmaf(ha.x, ha.x, fmaf(ha.y, ha.y, fmaf(ha.z, ha.z, fmaf(ha.w, ha.w, aH))));
        aE_ = fmaf(ha.x, e.x, fmaf(ha.y, e.y, fmaf(ha.z, e.z, fmaf(ha.w, e.w, aE_))));
        aC_ = fmaf(ha.x, c.x, fmaf(ha.y, c.y, fmaf(ha.z, c.z, fmaf(ha.w, c.w, aC_))));
        aN_ = fmaf(ha.x, n.x, fmaf(ha.y, n.y, fmaf(ha.z, n.z, fmaf(ha.w, n.w, aN_))));
        bH  = fmaf(hb.x, hb.x, fmaf(hb.y, hb.y, fmaf(hb.z, hb.z, fmaf(hb.w, hb.w, bH))));
        bE_ = fmaf(hb.x, e.x, fmaf(hb.y, e.y, fmaf(hb.z, e.z, fmaf(hb.w, e.w, bE_))));
        bC_ = fmaf(hb.x, c.x, fmaf(hb.y, c.y, fmaf(hb.z, c.z, fmaf(hb.w, c.w, bC_))));
        bN_ = fmaf(hb.x, n.x, fmaf(hb.y, n.y, fmaf(hb.z, n.z, fmaf(hb.w, n.w, bN_))));
    }
    // butterfly reduce -> every lane holds full-warp totals
#pragma unroll
    for (int off = 16; off > 0; off >>= 1) {
        aH  += __shfl_xor_sync(0xFFFFFFFFu, aH,  off);
        aE_ += __shfl_xor_sync(0xFFFFFFFFu, aE_, off);
        aC_ += __shfl_xor_sync(0xFFFFFFFFu, aC_, off);
        aN_ += __shfl_xor_sync(0xFFFFFFFFu, aN_, off);
        bH  += __shfl_xor_sync(0xFFFFFFFFu, bH,  off);
        bE_ += __shfl_xor_sync(0xFFFFFFFFu, bE_, off);
        bC_ += __shfl_xor_sync(0xFFFFFFFFu, bC_, off);
        bN_ += __shfl_xor_sync(0xFFFFFFFFu, bN_, off);
    }

    // ---- scalar 6-layer recurrence, both rows in parallel on half-warps ----
    const bool hi  = (lane >= 16);        // lanes 16-31 compute row B
    const int  row = hi ? rowB : rowA;
    const float g00 = hi ? bH  : aH;
    const float dE  = hi ? bE_ : aE_;
    const float dC  = hi ? bC_ : aC_;
    const float dN  = hi ? bN_ : aN_;

    const float invn0 = g_invn[0], invn1 = g_invn[1], invn2 = g_invn[2];
    float g0[3] = { dE * invn0, dC * invn1, dN * invn2 };
    float D[9];
#pragma unroll
    for (int j = 0; j < 9; j++) D[j] = g_D[j];

    float c0 = 1.f;
    float cc[3] = { 0.f, 0.f, 0.f };
    const float str[3] = { 0.1f, 0.1f, 0.05f };

#pragma unroll
    for (int l = 0; l < NLAYERS; l++) {
        float hd[3];
#pragma unroll
        for (int k = 0; k < 3; k++)
            hd[k] = c0 * g0[k] + cc[0] * D[0 * 3 + k] + cc[1] * D[1 * 3 + k] + cc[2] * D[2 * 3 + k];
        float hh = c0 * (c0 * g00 + cc[0] * g0[0] + cc[1] * g0[1] + cc[2] * g0[2])
                 + cc[0] * hd[0] + cc[1] * hd[1] + cc[2] * hd[2];
        float inv = rsqrtf(fmaxf(hh, 1e-24f));   // 1/||h||

        float a[3];
#pragma unroll
        for (int k = 0; k < 3; k++) {
            float align = hd[k] * inv;
            float dv    = 1.f - align;
            float tens  = fmaxf(dv, 0.f);
            if ((lane & 15) == 0) {              // lane 0 -> row A, lane 16 -> row B
                size_t ti = (size_t)l * (BATCH * 3) + (size_t)row * 3 + k;
                __stcs(out + TRACE_A + ti, align);
                __stcs(out + TRACE_D + ti, dv);
                __stcs(out + TRACE_T + ti, tens);
            }
            float msq = fmaxf(hh - 2.f * hd[k] + D[k * 3 + k], 1e-24f);
            a[k] = str[k] * dv * rsqrtf(msq);    // str*dv/||h - dir_k||
        }
        float f = 1.f - (a[0] + a[1] + a[2]);
        c0 *= f;
        cc[0] = cc[0] * f + a[0];
        cc[1] = cc[1] * f + a[1];
        cc[2] = cc[2] * f + a[2];

        // ||h_new|| via Gram quadratic form; clamp to MAXNORM
        float hd2[3];
#pragma unroll
        for (int k = 0; k < 3; k++)
            hd2[k] = c0 * g0[k] + cc[0] * D[0 * 3 + k] + cc[1] * D[1 * 3 + k] + cc[2] * D[2 * 3 + k];
        float hh2 = c0 * (c0 * g00 + cc[0] * g0[0] + cc[1] * g0[1] + cc[2] * g0[2])
                  + cc[0] * hd2[0] + cc[1] * hd2[1] + cc[2] * hd2[2];
        float rn = rsqrtf(fmaxf(hh2, 1e-24f));
        float nn = hh2 * rn;                     // ||h_new||
        if (nn > MAXNORM) {
            float scl = MAXNORM * rn;            // 10/||h||
            c0 *= scl; cc[0] *= scl; cc[1] *= scl; cc[2] *= scl;
        }
    }
    float wE = cc[0] * invn0, wC = cc[1] * invn1, wN = cc[2] * invn2;

    // broadcast both rows' coefficients to all lanes
    const float c0A = __shfl_sync(0xFFFFFFFFu, c0, 0);
    const float wEA = __shfl_sync(0xFFFFFFFFu, wE, 0);
    const float wCA = __shfl_sync(0xFFFFFFFFu, wC, 0);
    const float wNA = __shfl_sync(0xFFFFFFFFu, wN, 0);
    const float c0B = __shfl_sync(0xFFFFFFFFu, c0, 16);
    const float wEB = __shfl_sync(0xFFFFFFFFu, wE, 16);
    const float wCB = __shfl_sync(0xFFFFFFFFu, wC, 16);
    const float wNB = __shfl_sync(0xFFFFFFFFu, wN, 16);

    // ---- pass 2: both rows, anchors loaded once per iteration ----
    float4* oa = (float4*)(out + (size_t)rowA * DIM);
    float4* ob = (float4*)(out + (size_t)rowB * DIM);
#pragma unroll 2
    for (int it = 0; it < DIM / 4 / 32; it++) {
        int i = it * 32 + lane;
        float4 ha = __ldcs(&hra[i]);             // last use of rows
        float4 hb = __ldcs(&hrb[i]);
        float4 e = e4[i], c = c4[i], n = n4[i];
        float4 ra, rb;
        ra.x = fmaf(c0A, ha.x, fmaf(wEA, e.x, fmaf(wCA, c.x, wNA * n.x)));
        ra.y = fmaf(c0A, ha.y, fmaf(wEA, e.y, fmaf(wCA, c.y, wNA * n.y)));
        ra.z = fmaf(c0A, ha.z, fmaf(wEA, e.z, fmaf(wCA, c.z, wNA * n.z)));
        ra.w = fmaf(c0A, ha.w, fmaf(wEA, e.w, fmaf(wCA, c.w, wNA * n.w)));
        rb.x = fmaf(c0B, hb.x, fmaf(wEB, e.x, fmaf(wCB, c.x, wNB * n.x)));
        rb.y = fmaf(c0B, hb.y, fmaf(wEB, e.y, fmaf(wCB, c.y, wNB * n.y)));
        rb.z = fmaf(c0B, hb.z, fmaf(wEB, e.z, fmaf(wCB, c.z, wNB * n.z)));
        rb.w = fmaf(c0B, hb.w, fmaf(wEB, e.w, fmaf(wCB, c.w, wNB * n.w)));
        __stcs(&oa[i], ra);
        __stcs(&ob[i], rb);
    }
}

extern "C" void kernel_launch(void* const* d_in, const int* in_sizes, int n_in,
                              void* d_out, int out_size) {
    const float* h0 = (const float*)d_in[0];
    const float* aE = (const float*)d_in[1];
    const float* aC = (const float*)d_in[2];
    const float* aN = (const float*)d_in[3];
    float* out = (float*)d_out;

    prep_kernel<<<1, 256>>>(aE, aC, aN);
    // 4096 warps = 1024 blocks x 128 thr; warp w handles rows w and w+4096.
    collapse_kernel<<<NWARPS / 4, 128>>>(h0, aE, aC, aN, out);
}